// round 15
// baseline (speedup 1.0000x reference)
#include <cuda_runtime.h>

#define N_NODES 100000
#define N_EDGES 3200000
#define EPS_F 1e-6f
#define EDGE_BLOCKS 1184   // 148 SMs x 8 resident blocks: ONE wave, co-resident
#define EDGE_THREADS 256

// Scratch (no allocations allowed). Zero at module load; the kernel resets
// everything it dirties so every graph replay starts clean.
__device__ float    g_node_sum[N_NODES];        // N_NODES % 4 == 0
__device__ double   g_acc[5];                   // p0, p1, p0^2, p1^2, nsum^2
__device__ unsigned g_done1;
__device__ unsigned g_done2;

__device__ __forceinline__ float warp_sum(float v) {
    #pragma unroll
    for (int o = 16; o; o >>= 1) v += __shfl_xor_sync(0xffffffffu, v, o);
    return v;
}

// Single fused kernel. Phase 1: proven R5 edge loop (fire-and-forget REDG
// atomics, NO per-thread fence). Phase 2: thread-0-only fence + counter +
// spin = grid sync (safe: all EDGE_BLOCKS are co-resident by construction).
// Phase 3: cooperative slice reduction of node_sum^2 across the whole grid.
// Phase 4: last block finalizes and resets scratch.
__global__ void __launch_bounds__(EDGE_THREADS) fused_kernel(
    const float* __restrict__ node_features,
    const int*   __restrict__ edge_index,
    const float* __restrict__ edge_logits,
    const float2* __restrict__ edge_params,
    float* __restrict__ out)
{
    // ---------------- Phase 1: edge loop (unchanged hot path) ----------------
    float s0 = 0.f, s1 = 0.f, q0 = 0.f, q1 = 0.f;

    const int stride = gridDim.x * blockDim.x;
    for (int e = blockIdx.x * blockDim.x + threadIdx.x; e < N_EDGES; e += stride) {
        int src = edge_index[e];
        int dst = edge_index[N_EDGES + e];
        float2 p  = edge_params[e];
        float  lg = edge_logits[e];

        float prob = 1.0f / (1.0f + __expf(-lg));

        float vs = node_features[src * 4];   // column 0, row stride 4
        float vd = node_features[dst * 4];
        float vdiff = fabsf(vs - vd);
        float cur = __fdividef(vdiff, p.x + p.y + EPS_F) * prob;

        atomicAdd(&g_node_sum[dst],  cur);
        atomicAdd(&g_node_sum[src], -cur);

        s0 += p.x;  s1 += p.y;
        q0 += p.x * p.x;  q1 += p.y * p.y;
    }

    // Block reduction of moment accumulators -> double atomics (thread 0).
    __shared__ float sm[4][8];
    int lane = threadIdx.x & 31;
    int wid  = threadIdx.x >> 5;

    s0 = warp_sum(s0); s1 = warp_sum(s1); q0 = warp_sum(q0); q1 = warp_sum(q1);
    if (lane == 0) { sm[0][wid] = s0; sm[1][wid] = s1; sm[2][wid] = q0; sm[3][wid] = q1; }
    __syncthreads();
    if (wid == 0) {
        float a = (lane < 8) ? sm[0][lane] : 0.f;
        float b = (lane < 8) ? sm[1][lane] : 0.f;
        float c = (lane < 8) ? sm[2][lane] : 0.f;
        float d = (lane < 8) ? sm[3][lane] : 0.f;
        a = warp_sum(a); b = warp_sum(b); c = warp_sum(c); d = warp_sum(d);
        if (lane == 0) {
            atomicAdd(&g_acc[0], (double)a);
            atomicAdd(&g_acc[1], (double)b);
            atomicAdd(&g_acc[2], (double)c);
            atomicAdd(&g_acc[3], (double)d);
        }
    }

    // ---------------- Phase 2: grid sync (thread-0-only fence) ----------------
    // __syncthreads gives CTA-scope visibility of all 256 threads' REDs;
    // thread 0's cumulative fence.gpu promotes them gpu-wide before the
    // counter increment. One MEMBAR per BLOCK, not per thread (R6-R8 bug).
    __syncthreads();
    if (threadIdx.x == 0) {
        __threadfence();
        atomicAdd(&g_done1, 1u);
        volatile unsigned* vd = &g_done1;
        while (*vd < (unsigned)EDGE_BLOCKS) { __nanosleep(64); }
        __threadfence();   // acquire side
    }
    __syncthreads();

    // ---------------- Phase 3: cooperative node_sum^2 reduction ----------------
    // One float4 per thread; 25000 float4 spread over the first ~98 blocks.
    float4* ns4 = (float4*)g_node_sum;
    const int n4 = N_NODES / 4;   // 25000

    float acc = 0.f;
    int i = blockIdx.x * blockDim.x + threadIdx.x;
    if (i < n4) {
        float4 v = ns4[i];
        ns4[i] = make_float4(0.f, 0.f, 0.f, 0.f);   // self-clean for replay
        acc = v.x * v.x + v.y * v.y + v.z * v.z + v.w * v.w;
    }

    __shared__ float smn[8];
    acc = warp_sum(acc);
    if (lane == 0) smn[wid] = acc;
    __syncthreads();

    // ---------------- Phase 4: counter 2 + finalize (last block) ----------------
    if (threadIdx.x == 0) {
        float a = 0.f;
        #pragma unroll
        for (int w = 0; w < 8; w++) a += smn[w];
        if (a != 0.f) atomicAdd(&g_acc[4], (double)a);
        __threadfence();
        unsigned t = atomicAdd(&g_done2, 1u);
        if (t == (unsigned)(EDGE_BLOCKS - 1)) {
            __threadfence();
            double sum0 = g_acc[0], sum1 = g_acc[1];
            double sq0  = g_acc[2], sq1  = g_acc[3];
            double nsq  = g_acc[4];
            const double E = (double)N_EDGES;
            double var0 = (sq0 - sum0 * sum0 / E) / (E - 1.0);
            double var1 = (sq1 - sum1 * sum1 / E) / (E - 1.0);
            double kvl = 0.5 * (var0 + var1);
            double kcl = nsq / (double)N_NODES;
            out[0] = (float)(kcl + kvl);

            // Reset scratch for the next replay (g_node_sum already cleaned).
            g_acc[0] = 0.0; g_acc[1] = 0.0; g_acc[2] = 0.0;
            g_acc[3] = 0.0; g_acc[4] = 0.0;
            g_done1 = 0u;
            g_done2 = 0u;
        }
    }
}

extern "C" void kernel_launch(void* const* d_in, const int* in_sizes, int n_in,
                              void* d_out, int out_size)
{
    const float*  node_features = (const float*)d_in[0];
    const int*    edge_index    = (const int*)d_in[1];
    const float*  edge_logits   = (const float*)d_in[2];
    const float2* edge_params   = (const float2*)d_in[3];
    float* out = (float*)d_out;

    (void)in_sizes; (void)n_in; (void)out_size;

    fused_kernel<<<EDGE_BLOCKS, EDGE_THREADS>>>(node_features, edge_index,
                                                edge_logits, edge_params, out);
}

// round 16
// speedup vs baseline: 1.2277x; 1.2277x over previous
#include <cuda_runtime.h>

#define N_NODES 100000
#define N_EDGES 3200000
#define EPS_F 1e-6f
#define EDGE_BLOCKS 1184   // 148 SMs x 8 resident blocks: exactly one wave
#define EDGE_THREADS 256
#define NODE_BLOCKS 98     // 98 x 256 = 25088 threads >= 25000 float4 slots
#define NODE_THREADS 256

// Scratch (no allocations allowed). Zero at module load; the tail kernel
// re-zeroes everything it dirties, so every graph replay starts clean.
__device__ float    g_node_sum[N_NODES];        // N_NODES % 4 == 0
__device__ double   g_acc[5];                   // p0, p1, p0^2, p1^2, nsum^2
__device__ unsigned g_done;

__device__ __forceinline__ float warp_sum(float v) {
    #pragma unroll
    for (int o = 16; o; o >>= 1) v += __shfl_xor_sync(0xffffffffu, v, o);
    return v;
}

// Proven edge body (R5/R11): scalar grid-stride loop, fire-and-forget REDG
// atomics. CRITICAL INVARIANT (5 experiments of evidence): this kernel must
// contain NO readback of g_node_sum, NO spin, and NO fence on the thread
// path of the hot loop — violating this costs ~25-50 us.
__global__ void __launch_bounds__(EDGE_THREADS) edge_kernel(
    const float* __restrict__ node_features,
    const int*   __restrict__ edge_index,
    const float* __restrict__ edge_logits,
    const float2* __restrict__ edge_params)
{
    float s0 = 0.f, s1 = 0.f, q0 = 0.f, q1 = 0.f;

    const int stride = gridDim.x * blockDim.x;
    for (int e = blockIdx.x * blockDim.x + threadIdx.x; e < N_EDGES; e += stride) {
        int src = edge_index[e];
        int dst = edge_index[N_EDGES + e];
        float2 p  = edge_params[e];
        float  lg = edge_logits[e];

        float prob = 1.0f / (1.0f + __expf(-lg));

        float vs = node_features[src * 4];   // column 0, row stride 4
        float vd = node_features[dst * 4];
        float vdiff = fabsf(vs - vd);
        float cur = __fdividef(vdiff, p.x + p.y + EPS_F) * prob;

        atomicAdd(&g_node_sum[dst],  cur);
        atomicAdd(&g_node_sum[src], -cur);

        s0 += p.x;  s1 += p.y;
        q0 += p.x * p.x;  q1 += p.y * p.y;
    }

    // Block reduction of the moment accumulators -> double atomics.
    __shared__ float sm[4][8];
    int lane = threadIdx.x & 31;
    int wid  = threadIdx.x >> 5;

    s0 = warp_sum(s0); s1 = warp_sum(s1); q0 = warp_sum(q0); q1 = warp_sum(q1);
    if (lane == 0) { sm[0][wid] = s0; sm[1][wid] = s1; sm[2][wid] = q0; sm[3][wid] = q1; }
    __syncthreads();
    if (wid == 0) {
        float a = (lane < 8) ? sm[0][lane] : 0.f;
        float b = (lane < 8) ? sm[1][lane] : 0.f;
        float c = (lane < 8) ? sm[2][lane] : 0.f;
        float d = (lane < 8) ? sm[3][lane] : 0.f;
        a = warp_sum(a); b = warp_sum(b); c = warp_sum(c); d = warp_sum(d);
        if (lane == 0) {
            atomicAdd(&g_acc[0], (double)a);
            atomicAdd(&g_acc[1], (double)b);
            atomicAdd(&g_acc[2], (double)c);
            atomicAdd(&g_acc[3], (double)d);
        }
    }
}

// Tail: one float4 per thread (no loop), self-cleaning zero store, block
// shuffle-reduce, thread-0-only fence + done-counter; last block finalizes
// the scalar and resets the accumulators for the next replay.
__global__ void __launch_bounds__(NODE_THREADS) node_final_kernel(float* __restrict__ out) {
    float4* ns4 = (float4*)g_node_sum;
    const int n4 = N_NODES / 4;   // 25000

    int i = blockIdx.x * blockDim.x + threadIdx.x;
    float acc = 0.f;
    if (i < n4) {
        float4 v = ns4[i];
        ns4[i] = make_float4(0.f, 0.f, 0.f, 0.f);   // self-clean for next replay
        acc = v.x * v.x + v.y * v.y + v.z * v.z + v.w * v.w;
    }

    __shared__ float sm[NODE_THREADS / 32];
    int lane = threadIdx.x & 31;
    int wid  = threadIdx.x >> 5;
    acc = warp_sum(acc);
    if (lane == 0) sm[wid] = acc;
    __syncthreads();

    __shared__ unsigned s_is_last;
    if (threadIdx.x == 0) {
        float a = 0.f;
        #pragma unroll
        for (int w = 0; w < NODE_THREADS / 32; w++) a += sm[w];
        atomicAdd(&g_acc[4], (double)a);
        __threadfence();
        s_is_last = (atomicAdd(&g_done, 1u) == (unsigned)(gridDim.x - 1));
    }
    __syncthreads();
    if (!s_is_last) return;

    if (threadIdx.x == 0) {
        __threadfence();   // acquire: see all blocks' g_acc[4] contributions
        double sum0 = g_acc[0], sum1 = g_acc[1];
        double sq0  = g_acc[2], sq1  = g_acc[3];
        double nsq  = g_acc[4];
        const double E = (double)N_EDGES;
        double var0 = (sq0 - sum0 * sum0 / E) / (E - 1.0);
        double var1 = (sq1 - sum1 * sum1 / E) / (E - 1.0);
        double kvl = 0.5 * (var0 + var1);
        double kcl = nsq / (double)N_NODES;
        out[0] = (float)(kcl + kvl);

        // Reset accumulators for the next replay.
        g_acc[0] = 0.0; g_acc[1] = 0.0; g_acc[2] = 0.0;
        g_acc[3] = 0.0; g_acc[4] = 0.0;
        g_done = 0u;
    }
}

extern "C" void kernel_launch(void* const* d_in, const int* in_sizes, int n_in,
                              void* d_out, int out_size)
{
    const float*  node_features = (const float*)d_in[0];
    const int*    edge_index    = (const int*)d_in[1];
    const float*  edge_logits   = (const float*)d_in[2];
    const float2* edge_params   = (const float2*)d_in[3];
    float* out = (float*)d_out;

    (void)in_sizes; (void)n_in; (void)out_size;

    edge_kernel<<<EDGE_BLOCKS, EDGE_THREADS>>>(node_features, edge_index,
                                               edge_logits, edge_params);
    node_final_kernel<<<NODE_BLOCKS, NODE_THREADS>>>(out);
}

// round 17
// speedup vs baseline: 1.2678x; 1.0327x over previous
#include <cuda_runtime.h>

#define N_NODES 100000
#define N_EDGES 3200000
#define EPS_F 1e-6f
#define EDGE_BLOCKS 1216   // 152 SMs (GB300) x 8 resident blocks: one balanced wave
#define EDGE_THREADS 256
#define NODE_BLOCKS 98     // 98 x 256 = 25088 threads >= 25000 float4 slots
#define NODE_THREADS 256

// Scratch (no allocations allowed). Zero at module load; the tail kernel
// re-zeroes everything it dirties, so every graph replay starts clean.
__device__ float    g_node_sum[N_NODES];        // N_NODES % 4 == 0
__device__ double   g_acc[5];                   // p0, p1, p0^2, p1^2, nsum^2
__device__ unsigned g_done;

__device__ __forceinline__ float warp_sum(float v) {
    #pragma unroll
    for (int o = 16; o; o >>= 1) v += __shfl_xor_sync(0xffffffffu, v, o);
    return v;
}

// Proven edge body (R5/R11): scalar grid-stride loop, fire-and-forget REDG
// atomics. CRITICAL INVARIANT (5 experiments of evidence): this kernel must
// contain NO readback of g_node_sum, NO spin, and NO fence on the thread
// path of the hot loop — violating this costs ~25-50 us.
__global__ void __launch_bounds__(EDGE_THREADS) edge_kernel(
    const float* __restrict__ node_features,
    const int*   __restrict__ edge_index,
    const float* __restrict__ edge_logits,
    const float2* __restrict__ edge_params)
{
    float s0 = 0.f, s1 = 0.f, q0 = 0.f, q1 = 0.f;

    const int stride = gridDim.x * blockDim.x;
    for (int e = blockIdx.x * blockDim.x + threadIdx.x; e < N_EDGES; e += stride) {
        int src = edge_index[e];
        int dst = edge_index[N_EDGES + e];
        float2 p  = edge_params[e];
        float  lg = edge_logits[e];

        float prob = 1.0f / (1.0f + __expf(-lg));

        float vs = node_features[src * 4];   // column 0, row stride 4
        float vd = node_features[dst * 4];
        float vdiff = fabsf(vs - vd);
        float cur = __fdividef(vdiff, p.x + p.y + EPS_F) * prob;

        atomicAdd(&g_node_sum[dst],  cur);
        atomicAdd(&g_node_sum[src], -cur);

        s0 += p.x;  s1 += p.y;
        q0 += p.x * p.x;  q1 += p.y * p.y;
    }

    // Block reduction of the moment accumulators -> double atomics.
    __shared__ float sm[4][8];
    int lane = threadIdx.x & 31;
    int wid  = threadIdx.x >> 5;

    s0 = warp_sum(s0); s1 = warp_sum(s1); q0 = warp_sum(q0); q1 = warp_sum(q1);
    if (lane == 0) { sm[0][wid] = s0; sm[1][wid] = s1; sm[2][wid] = q0; sm[3][wid] = q1; }
    __syncthreads();
    if (wid == 0) {
        float a = (lane < 8) ? sm[0][lane] : 0.f;
        float b = (lane < 8) ? sm[1][lane] : 0.f;
        float c = (lane < 8) ? sm[2][lane] : 0.f;
        float d = (lane < 8) ? sm[3][lane] : 0.f;
        a = warp_sum(a); b = warp_sum(b); c = warp_sum(c); d = warp_sum(d);
        if (lane == 0) {
            atomicAdd(&g_acc[0], (double)a);
            atomicAdd(&g_acc[1], (double)b);
            atomicAdd(&g_acc[2], (double)c);
            atomicAdd(&g_acc[3], (double)d);
        }
    }
}

// Tail: one float4 per thread (no loop), self-cleaning zero store, block
// shuffle-reduce, thread-0-only fence + done-counter; last block finalizes
// the scalar and resets the accumulators for the next replay.
__global__ void __launch_bounds__(NODE_THREADS) node_final_kernel(float* __restrict__ out) {
    float4* ns4 = (float4*)g_node_sum;
    const int n4 = N_NODES / 4;   // 25000

    int i = blockIdx.x * blockDim.x + threadIdx.x;
    float acc = 0.f;
    if (i < n4) {
        float4 v = ns4[i];
        ns4[i] = make_float4(0.f, 0.f, 0.f, 0.f);   // self-clean for next replay
        acc = v.x * v.x + v.y * v.y + v.z * v.z + v.w * v.w;
    }

    __shared__ float sm[NODE_THREADS / 32];
    int lane = threadIdx.x & 31;
    int wid  = threadIdx.x >> 5;
    acc = warp_sum(acc);
    if (lane == 0) sm[wid] = acc;
    __syncthreads();

    __shared__ unsigned s_is_last;
    if (threadIdx.x == 0) {
        float a = 0.f;
        #pragma unroll
        for (int w = 0; w < NODE_THREADS / 32; w++) a += sm[w];
        atomicAdd(&g_acc[4], (double)a);
        __threadfence();
        s_is_last = (atomicAdd(&g_done, 1u) == (unsigned)(gridDim.x - 1));
    }
    __syncthreads();
    if (!s_is_last) return;

    if (threadIdx.x == 0) {
        __threadfence();   // acquire: see all blocks' g_acc[4] contributions
        double sum0 = g_acc[0], sum1 = g_acc[1];
        double sq0  = g_acc[2], sq1  = g_acc[3];
        double nsq  = g_acc[4];
        const double E = (double)N_EDGES;
        double var0 = (sq0 - sum0 * sum0 / E) / (E - 1.0);
        double var1 = (sq1 - sum1 * sum1 / E) / (E - 1.0);
        double kvl = 0.5 * (var0 + var1);
        double kcl = nsq / (double)N_NODES;
        out[0] = (float)(kcl + kvl);

        // Reset accumulators for the next replay.
        g_acc[0] = 0.0; g_acc[1] = 0.0; g_acc[2] = 0.0;
        g_acc[3] = 0.0; g_acc[4] = 0.0;
        g_done = 0u;
    }
}

extern "C" void kernel_launch(void* const* d_in, const int* in_sizes, int n_in,
                              void* d_out, int out_size)
{
    const float*  node_features = (const float*)d_in[0];
    const int*    edge_index    = (const int*)d_in[1];
    const float*  edge_logits   = (const float*)d_in[2];
    const float2* edge_params   = (const float2*)d_in[3];
    float* out = (float*)d_out;

    (void)in_sizes; (void)n_in; (void)out_size;

    edge_kernel<<<EDGE_BLOCKS, EDGE_THREADS>>>(node_features, edge_index,
                                               edge_logits, edge_params);
    node_final_kernel<<<NODE_BLOCKS, NODE_THREADS>>>(out);
}